// round 1
// baseline (speedup 1.0000x reference)
#include <cuda_runtime.h>
#include <math.h>

#define DIMM 1024
#define SEQ  2048
#define BATCH 4
#define NH   16
#define HD   64
#define N_QKV (3*DIMM)   // 3072

// Scratch (allocation-free rule: __device__ globals). 4 x 33.5 MB.
__device__ float g_q[BATCH*NH*SEQ*HD];
__device__ float g_k[BATCH*NH*SEQ*HD];
__device__ float g_v[BATCH*NH*SEQ*HD];
__device__ float g_o[BATCH*NH*SEQ*HD];

// ---------------------------------------------------------------------------
// GEMM1: qkv = x @ w_qkv, epilogue scatters into per-head [B,H,S,D] Q/K/V.
// M=8192, N=3072, K=1024. BM=BN=128, BK=16, 256 threads, 8x8 per thread.
// ---------------------------------------------------------------------------
__global__ __launch_bounds__(256) void gemm_qkv_kernel(const float* __restrict__ X,
                                                       const float* __restrict__ W)
{
    __shared__ float Xs[16][132];   // transposed: Xs[k][m], padded
    __shared__ float Ws[16][128];   // Ws[k][n]

    const int n0 = blockIdx.x * 128;
    const int m0 = blockIdx.y * 128;
    const int t  = threadIdx.x;
    const int tx = t & 15, ty = t >> 4;

    float acc[8][8];
#pragma unroll
    for (int i = 0; i < 8; i++)
#pragma unroll
        for (int j = 0; j < 8; j++) acc[i][j] = 0.0f;

    for (int k0 = 0; k0 < DIMM; k0 += 16) {
#pragma unroll
        for (int l = 0; l < 2; l++) {
            int f = t + l * 256;            // 512 float4 total
            int r = f >> 2, c4 = f & 3;
            float4 xv = *(const float4*)&X[(size_t)(m0 + r) * DIMM + k0 + c4 * 4];
            Xs[c4*4+0][r] = xv.x; Xs[c4*4+1][r] = xv.y;
            Xs[c4*4+2][r] = xv.z; Xs[c4*4+3][r] = xv.w;
        }
#pragma unroll
        for (int l = 0; l < 2; l++) {
            int f = t + l * 256;
            int kr = f >> 5, c4 = f & 31;
            *(float4*)&Ws[kr][c4*4] =
                *(const float4*)&W[(size_t)(k0 + kr) * N_QKV + n0 + c4 * 4];
        }
        __syncthreads();
#pragma unroll
        for (int kk = 0; kk < 16; kk++) {
            float a[8], b[8];
            *(float4*)&a[0] = *(float4*)&Xs[kk][ty*8];
            *(float4*)&a[4] = *(float4*)&Xs[kk][ty*8+4];
            *(float4*)&b[0] = *(float4*)&Ws[kk][tx*8];
            *(float4*)&b[4] = *(float4*)&Ws[kk][tx*8+4];
#pragma unroll
            for (int i = 0; i < 8; i++)
#pragma unroll
                for (int j = 0; j < 8; j++) acc[i][j] += a[i] * b[j];
        }
        __syncthreads();
    }

    // Epilogue: n -> (part, head h, dim d). Whole 8-col strip stays in one head.
    const int nb   = n0 + tx * 8;
    const int part = nb >> 10;           // 0:q 1:k 2:v
    const int w    = nb & 1023;
    const int h    = w >> 6;
    const int d0   = w & 63;
    float* dst = (part == 0) ? g_q : (part == 1) ? g_k : g_v;
#pragma unroll
    for (int i = 0; i < 8; i++) {
        int m = m0 + ty * 8 + i;
        int b = m >> 11, s = m & 2047;
        size_t off = ((size_t)(b * NH + h) * SEQ + s) * HD + d0;
        *(float4*)&dst[off]     = make_float4(acc[i][0], acc[i][1], acc[i][2], acc[i][3]);
        *(float4*)&dst[off + 4] = make_float4(acc[i][4], acc[i][5], acc[i][6], acc[i][7]);
    }
}

// ---------------------------------------------------------------------------
// Flash-style attention, fp32. One block = one (b,h) and 64 query rows.
// BR=BC=64. 256 threads as 16x16 grid, 4x4 tile each.
// Shared: Qs row-major, KPs (K transposed over d, reused as P), Vs row-major.
// Exactly 48 KB static shared.
// ---------------------------------------------------------------------------
__global__ __launch_bounds__(256) void attn_kernel()
{
    __shared__ float Qs [64][64];
    __shared__ float KPs[64][64];
    __shared__ float Vs [64][64];

    const int bh = blockIdx.y;
    const int q0 = blockIdx.x * 64;
    const float* Qg = g_q + (size_t)bh * SEQ * HD;
    const float* Kg = g_k + (size_t)bh * SEQ * HD;
    const float* Vg = g_v + (size_t)bh * SEQ * HD;
    float*       Og = g_o + (size_t)bh * SEQ * HD;

    const int t  = threadIdx.x;
    const int tx = t & 15, ty = t >> 4;
    const float scale = 0.125f;   // 64^-0.5

    // Load Q tile, pre-scaled.
#pragma unroll
    for (int l = 0; l < 4; l++) {
        int f = t + l * 256;            // 1024 float4
        int r = f >> 4, c4 = f & 15;
        float4 qv = *(const float4*)&Qg[(size_t)(q0 + r) * HD + c4 * 4];
        qv.x *= scale; qv.y *= scale; qv.z *= scale; qv.w *= scale;
        *(float4*)&Qs[r][c4*4] = qv;
    }

    float m_run[4], l_run[4], oacc[4][4];
#pragma unroll
    for (int a = 0; a < 4; a++) {
        m_run[a] = -1e30f; l_run[a] = 0.0f;
#pragma unroll
        for (int b = 0; b < 4; b++) oacc[a][b] = 0.0f;
    }

    for (int j0 = 0; j0 < SEQ; j0 += 64) {
        __syncthreads();   // prev-iter P/V reads done (also fences Q load, iter 0)
        // Load K (transposed into KPs[d][j]) and V (row-major).
#pragma unroll
        for (int l = 0; l < 4; l++) {
            int f = t + l * 256;
            int r = f >> 4, c4 = f & 15;
            float4 kv = *(const float4*)&Kg[(size_t)(j0 + r) * HD + c4 * 4];
            KPs[c4*4+0][r] = kv.x; KPs[c4*4+1][r] = kv.y;
            KPs[c4*4+2][r] = kv.z; KPs[c4*4+3][r] = kv.w;
            *(float4*)&Vs[r][c4*4] = *(const float4*)&Vg[(size_t)(j0 + r) * HD + c4 * 4];
        }
        __syncthreads();

        // S = Q @ K^T  (per-thread 4x4 tile)
        float s[4][4];
#pragma unroll
        for (int a = 0; a < 4; a++)
#pragma unroll
            for (int b = 0; b < 4; b++) s[a][b] = 0.0f;

#pragma unroll
        for (int d4 = 0; d4 < 16; d4++) {
            float qr[4][4], kr[4][4];
#pragma unroll
            for (int a = 0; a < 4; a++) {
                float4 v = *(float4*)&Qs[ty*4+a][d4*4];
                qr[a][0] = v.x; qr[a][1] = v.y; qr[a][2] = v.z; qr[a][3] = v.w;
            }
#pragma unroll
            for (int dd = 0; dd < 4; dd++) {
                float4 v = *(float4*)&KPs[d4*4+dd][tx*4];
                kr[dd][0] = v.x; kr[dd][1] = v.y; kr[dd][2] = v.z; kr[dd][3] = v.w;
            }
#pragma unroll
            for (int a = 0; a < 4; a++)
#pragma unroll
                for (int b = 0; b < 4; b++)
#pragma unroll
                    for (int dd = 0; dd < 4; dd++)
                        s[a][b] += qr[a][dd] * kr[dd][b];
        }

        // Online softmax (row groups = 16 tx-lanes within a warp half).
#pragma unroll
        for (int a = 0; a < 4; a++) {
            float mt = fmaxf(fmaxf(s[a][0], s[a][1]), fmaxf(s[a][2], s[a][3]));
            mt = fmaxf(mt, __shfl_xor_sync(0xffffffffu, mt, 1));
            mt = fmaxf(mt, __shfl_xor_sync(0xffffffffu, mt, 2));
            mt = fmaxf(mt, __shfl_xor_sync(0xffffffffu, mt, 4));
            mt = fmaxf(mt, __shfl_xor_sync(0xffffffffu, mt, 8));
            float m_new = fmaxf(m_run[a], mt);
            float fac   = __expf(m_run[a] - m_new);
            float ls = 0.0f;
#pragma unroll
            for (int b = 0; b < 4; b++) {
                s[a][b] = __expf(s[a][b] - m_new);
                ls += s[a][b];
            }
            ls += __shfl_xor_sync(0xffffffffu, ls, 1);
            ls += __shfl_xor_sync(0xffffffffu, ls, 2);
            ls += __shfl_xor_sync(0xffffffffu, ls, 4);
            ls += __shfl_xor_sync(0xffffffffu, ls, 8);
            l_run[a] = l_run[a] * fac + ls;
            m_run[a] = m_new;
#pragma unroll
            for (int b = 0; b < 4; b++) oacc[a][b] *= fac;
        }

        __syncthreads();   // all S-reads of KPs done
#pragma unroll
        for (int a = 0; a < 4; a++)
            *(float4*)&KPs[ty*4+a][tx*4] = make_float4(s[a][0], s[a][1], s[a][2], s[a][3]);
        __syncthreads();

        // O += P @ V
#pragma unroll
        for (int c4 = 0; c4 < 16; c4++) {
            float pr[4][4], vr[4][4];
#pragma unroll
            for (int a = 0; a < 4; a++) {
                float4 v = *(float4*)&KPs[ty*4+a][c4*4];
                pr[a][0] = v.x; pr[a][1] = v.y; pr[a][2] = v.z; pr[a][3] = v.w;
            }
#pragma unroll
            for (int cc = 0; cc < 4; cc++) {
                float4 v = *(float4*)&Vs[c4*4+cc][tx*4];
                vr[cc][0] = v.x; vr[cc][1] = v.y; vr[cc][2] = v.z; vr[cc][3] = v.w;
            }
#pragma unroll
            for (int a = 0; a < 4; a++)
#pragma unroll
                for (int b = 0; b < 4; b++)
#pragma unroll
                    for (int cc = 0; cc < 4; cc++)
                        oacc[a][b] += pr[a][cc] * vr[cc][b];
        }
    }

    // Finalize and store to g_o[b,h,s,d].
#pragma unroll
    for (int a = 0; a < 4; a++) {
        float inv = 1.0f / l_run[a];
        int r = q0 + ty * 4 + a;
        *(float4*)&Og[(size_t)r * HD + tx * 4] =
            make_float4(oacc[a][0]*inv, oacc[a][1]*inv, oacc[a][2]*inv, oacc[a][3]*inv);
    }
}

// ---------------------------------------------------------------------------
// GEMM2: out = g_o(viewed [8192,1024]) @ w_out + b_out.
// The reference's no-transpose reshape == contiguous [B,H,S,D] view: free.
// ---------------------------------------------------------------------------
__global__ __launch_bounds__(256) void gemm_out_kernel(const float* __restrict__ Wo,
                                                       const float* __restrict__ bias,
                                                       float* __restrict__ out)
{
    __shared__ float As[16][132];
    __shared__ float Bs[16][128];

    const int n0 = blockIdx.x * 128;
    const int m0 = blockIdx.y * 128;
    const int t  = threadIdx.x;
    const int tx = t & 15, ty = t >> 4;
    const float* A = g_o;   // [8192][1024] contiguous

    float acc[8][8];
#pragma unroll
    for (int i = 0; i < 8; i++)
#pragma unroll
        for (int j = 0; j < 8; j++) acc[i][j] = 0.0f;

    for (int k0 = 0; k0 < DIMM; k0 += 16) {
#pragma unroll
        for (int l = 0; l < 2; l++) {
            int f = t + l * 256;
            int r = f >> 2, c4 = f & 3;
            float4 av = *(const float4*)&A[(size_t)(m0 + r) * DIMM + k0 + c4 * 4];
            As[c4*4+0][r] = av.x; As[c4*4+1][r] = av.y;
            As[c4*4+2][r] = av.z; As[c4*4+3][r] = av.w;
        }
#pragma unroll
        for (int l = 0; l < 2; l++) {
            int f = t + l * 256;
            int kr = f >> 5, c4 = f & 31;
            *(float4*)&Bs[kr][c4*4] =
                *(const float4*)&Wo[(size_t)(k0 + kr) * DIMM + n0 + c4 * 4];
        }
        __syncthreads();
#pragma unroll
        for (int kk = 0; kk < 16; kk++) {
            float a[8], b[8];
            *(float4*)&a[0] = *(float4*)&As[kk][ty*8];
            *(float4*)&a[4] = *(float4*)&As[kk][ty*8+4];
            *(float4*)&b[0] = *(float4*)&Bs[kk][tx*8];
            *(float4*)&b[4] = *(float4*)&Bs[kk][tx*8+4];
#pragma unroll
            for (int i = 0; i < 8; i++)
#pragma unroll
                for (int j = 0; j < 8; j++) acc[i][j] += a[i] * b[j];
        }
        __syncthreads();
    }

    float4 bi0 = *(const float4*)&bias[n0 + tx * 8];
    float4 bi1 = *(const float4*)&bias[n0 + tx * 8 + 4];
#pragma unroll
    for (int i = 0; i < 8; i++) {
        int m = m0 + ty * 8 + i;
        size_t off = (size_t)m * DIMM + n0 + tx * 8;
        *(float4*)&out[off] = make_float4(acc[i][0]+bi0.x, acc[i][1]+bi0.y,
                                          acc[i][2]+bi0.z, acc[i][3]+bi0.w);
        *(float4*)&out[off+4] = make_float4(acc[i][4]+bi1.x, acc[i][5]+bi1.y,
                                            acc[i][6]+bi1.z, acc[i][7]+bi1.w);
    }
}

// ---------------------------------------------------------------------------
extern "C" void kernel_launch(void* const* d_in, const int* in_sizes, int n_in,
                              void* d_out, int out_size)
{
    const float* x     = (const float*)d_in[0];   // [4,2048,1024]
    const float* w_qkv = (const float*)d_in[1];   // [1024,3072]
    const float* w_out = (const float*)d_in[2];   // [1024,1024]
    const float* b_out = (const float*)d_in[3];   // [1024]
    float* out = (float*)d_out;                   // [4,2048,1024]

    dim3 g1(N_QKV / 128, (BATCH * SEQ) / 128);    // 24 x 64
    gemm_qkv_kernel<<<g1, 256>>>(x, w_qkv);

    dim3 g2(SEQ / 64, BATCH * NH);                // 32 x 64
    attn_kernel<<<g2, 256>>>();

    dim3 g3(DIMM / 128, (BATCH * SEQ) / 128);     // 8 x 64
    gemm_out_kernel<<<g3, 256>>>(w_out, b_out, out);
}

// round 6
// speedup vs baseline: 2.2461x; 2.2461x over previous
#include <cuda_runtime.h>
#include <cuda_bf16.h>
#include <stdint.h>

#define SEQ   2048
#define BATCH 4
#define NH    16
#define HD    64
#define DIMM  1024
#define GK    3072          // tripled K for compensated bf16
#define MTOT  8192
#define NKB   (GK/32)       // 96 k-blocks of 32

typedef __nv_bfloat16 bf16;

// ---------------- scratch (__device__ globals; referenced ONLY in device code)
__device__ bf16 g_q   [(size_t)64*SEQ*192];      // [bh][s][qh|ql|qh], pre-scaled
__device__ bf16 g_k   [(size_t)64*SEQ*192];      // [bh][s][kh|kh|kl]
__device__ bf16 g_v   [(size_t)64*2*SEQ*64];     // [bh][plane hi/lo][s][d]
__device__ bf16 g_Ax  [(size_t)MTOT*GK];         // split activations (x, later attn out)
__device__ bf16 g_Bqkv[(size_t)3072*GK];         // split+transposed w_qkv
__device__ bf16 g_Bout[(size_t)1024*GK];         // split+transposed w_out

// ---------------- small helpers ---------------------------------------------
__device__ __forceinline__ uint32_t smem_u32(const void* p) {
    uint32_t a;
    asm("{ .reg .u64 t; cvta.to.shared.u64 t, %1; cvt.u32.u64 %0, t; }"
        : "=r"(a) : "l"(p));
    return a;
}
// pack2(lo, hi): memory order [lo, hi]
__device__ __forceinline__ uint32_t pack2(float lo, float hi) {
    uint32_t r;
    asm("cvt.rn.bf16x2.f32 %0, %1, %2;" : "=r"(r) : "f"(hi), "f"(lo));
    return r;
}
__device__ __forceinline__ float lo_f(uint32_t x) { return __uint_as_float(x << 16); }
__device__ __forceinline__ float hi_f(uint32_t x) { return __uint_as_float(x & 0xffff0000u); }

__device__ __forceinline__ void ldsm_x4(uint32_t* r, uint32_t addr) {
    asm volatile("ldmatrix.sync.aligned.m8n8.x4.shared.b16 {%0,%1,%2,%3}, [%4];"
        : "=r"(r[0]), "=r"(r[1]), "=r"(r[2]), "=r"(r[3]) : "r"(addr));
}
__device__ __forceinline__ void ldsm_x4_t(uint32_t* r, uint32_t addr) {
    asm volatile("ldmatrix.sync.aligned.m8n8.x4.trans.shared.b16 {%0,%1,%2,%3}, [%4];"
        : "=r"(r[0]), "=r"(r[1]), "=r"(r[2]), "=r"(r[3]) : "r"(addr));
}
__device__ __forceinline__ void mma_bf16(float* d, const uint32_t* a, const uint32_t* b) {
    asm volatile(
        "mma.sync.aligned.m16n8k16.row.col.f32.bf16.bf16.f32 "
        "{%0,%1,%2,%3}, {%4,%5,%6,%7}, {%8,%9}, {%0,%1,%2,%3};"
        : "+f"(d[0]), "+f"(d[1]), "+f"(d[2]), "+f"(d[3])
        : "r"(a[0]), "r"(a[1]), "r"(a[2]), "r"(a[3]), "r"(b[0]), "r"(b[1]));
}
__device__ __forceinline__ void cp16(uint32_t s, const void* g) {
    asm volatile("cp.async.cg.shared.global [%0], [%1], 16;" :: "r"(s), "l"(g));
}
#define CP_COMMIT()  asm volatile("cp.async.commit_group;" ::: "memory")
#define CP_WAIT1()   asm volatile("cp.async.wait_group 1;" ::: "memory")
#define CP_WAIT0()   asm volatile("cp.async.wait_group 0;" ::: "memory")

__device__ __forceinline__ void split_bf16(float v, bf16& hi, bf16& lo) {
    hi = __float2bfloat16(v);
    lo = __float2bfloat16(v - __bfloat162float(hi));
}

// ---------------- conversion kernels ----------------------------------------
// x[m][0:1024] f32 -> g_Ax[m][0:3072] bf16 = [hi | lo | hi]
__global__ __launch_bounds__(256) void conv_split_kernel(const float* __restrict__ in)
{
    int idx = blockIdx.x * 256 + threadIdx.x;
    int m  = idx >> 8;
    int c4 = (idx & 255) << 2;
    float4 v = *(const float4*)(in + (size_t)m * DIMM + c4);
    bf16 h[4], l[4];
    split_bf16(v.x, h[0], l[0]); split_bf16(v.y, h[1], l[1]);
    split_bf16(v.z, h[2], l[2]); split_bf16(v.w, h[3], l[3]);
    size_t ro = (size_t)m * GK + c4;
    *(uint2*)(g_Ax + ro)        = *(uint2*)h;
    *(uint2*)(g_Ax + ro + 1024) = *(uint2*)l;
    *(uint2*)(g_Ax + ro + 2048) = *(uint2*)h;
}

// w[k][n] f32 -> B'[n][0:3072] bf16 = [hi | hi | lo]  (transpose + split)
// which=0 -> g_Bqkv (N=3072), which=1 -> g_Bout (N=1024)
__global__ void conv_w_kernel(const float* __restrict__ w, int N, int which)
{
    __shared__ float tile[32][33];
    bf16* outB = which ? g_Bout : g_Bqkv;
    int tx = threadIdx.x, ty = threadIdx.y;
    int k0 = blockIdx.x * 32, n0 = blockIdx.y * 32;
    tile[ty][tx] = w[(size_t)(k0 + ty) * N + n0 + tx];
    __syncthreads();
    float v = tile[tx][ty];
    int n = n0 + ty, k = k0 + tx;
    bf16 hi, lo;
    split_bf16(v, hi, lo);
    size_t ro = (size_t)n * GK + k;
    outB[ro]        = hi;
    outB[ro + 1024] = hi;
    outB[ro + 2048] = lo;
}

// ---------------- mma.sync GEMM ---------------------------------------------
// C[128x128] = g_Ax[M][GK] @ B'[N][GK]^T (compensated bf16, fp32 accum)
// mode 0: B=g_Bqkv, split-scatter into g_q/g_k/g_v.  mode 1: B=g_Bout, +bias -> Cout.
__global__ __launch_bounds__(256) void mma_gemm_kernel(const float* __restrict__ bias,
                                                       float* __restrict__ Cout,
                                                       int mode)
{
    __shared__ __align__(16) bf16 smA[2][128][40];
    __shared__ __align__(16) bf16 smB[2][128][40];

    const bf16* A = g_Ax;
    const bf16* B = mode ? g_Bout : g_Bqkv;

    const int t    = threadIdx.x;
    const int wid  = t >> 5;
    const int lane = t & 31;
    const int warp_m = wid & 1;
    const int warp_n = wid >> 1;
    const int n0 = blockIdx.x * 128;
    const int m0 = blockIdx.y * 128;

    const int lrow = t >> 1;
    const int lseg = (t & 1) * 16;
    const bf16* Ap = A + (size_t)(m0 + lrow) * GK + lseg;
    const bf16* Bp = B + (size_t)(n0 + lrow) * GK + lseg;

    float acc[4][4][4];
#pragma unroll
    for (int i = 0; i < 4; i++)
#pragma unroll
        for (int j = 0; j < 4; j++)
#pragma unroll
            for (int q = 0; q < 4; q++) acc[i][j][q] = 0.0f;

    uint32_t sA0 = smem_u32(&smA[0][lrow][lseg]);
    uint32_t sB0 = smem_u32(&smB[0][lrow][lseg]);
    const uint32_t stageA = 128 * 40 * 2;
    cp16(sA0,      Ap);       cp16(sA0 + 16, Ap + 8);
    cp16(sB0,      Bp);       cp16(sB0 + 16, Bp + 8);
    CP_COMMIT();

    const uint32_t aBase = smem_u32(&smA[0][0][0]);
    const uint32_t bBase = smem_u32(&smB[0][0][0]);

    for (int kb = 0; kb < NKB; kb++) {
        if (kb + 1 < NKB) {
            int st = (kb + 1) & 1;
            const bf16* Ak = Ap + (kb + 1) * 32;
            const bf16* Bk = Bp + (kb + 1) * 32;
            cp16(sA0 + st * stageA,      Ak);     cp16(sA0 + st * stageA + 16, Ak + 8);
            cp16(sB0 + st * stageA,      Bk);     cp16(sB0 + st * stageA + 16, Bk + 8);
            CP_COMMIT();
            CP_WAIT1();
        } else {
            CP_WAIT0();
        }
        __syncthreads();

        const uint32_t ab = aBase + (kb & 1) * stageA;
        const uint32_t bb = bBase + (kb & 1) * stageA;
#pragma unroll
        for (int ks = 0; ks < 2; ks++) {
            const int k0 = ks * 16;
            uint32_t afr[4][4];
#pragma unroll
            for (int mt = 0; mt < 4; mt++)
                ldsm_x4(afr[mt], ab + (((warp_m*64 + mt*16 + (lane & 15)) * 40)
                                       + k0 + (lane >> 4) * 8) * 2);
            uint32_t bfr[4][2];
#pragma unroll
            for (int ntp = 0; ntp < 4; ntp += 2) {
                uint32_t tmp[4];
                ldsm_x4(tmp, bb + (((warp_n*32 + ntp*8 + (lane >> 4)*8 + (lane & 7)) * 40)
                                   + k0 + ((lane >> 3) & 1) * 8) * 2);
                bfr[ntp][0] = tmp[0];   bfr[ntp][1] = tmp[1];
                bfr[ntp+1][0] = tmp[2]; bfr[ntp+1][1] = tmp[3];
            }
#pragma unroll
            for (int mt = 0; mt < 4; mt++)
#pragma unroll
                for (int nt = 0; nt < 4; nt++)
                    mma_bf16(acc[mt][nt], afr[mt], bfr[nt]);
        }
        __syncthreads();
    }

    // ---------------- epilogue ----------------
#pragma unroll
    for (int mt = 0; mt < 4; mt++) {
#pragma unroll
        for (int nt = 0; nt < 4; nt++) {
            int m_lo = m0 + warp_m*64 + mt*16 + (lane >> 2);
            int n    = n0 + warp_n*32 + nt*8 + 2*(lane & 3);
#pragma unroll
            for (int half = 0; half < 2; half++) {
                int m = m_lo + half * 8;
                float v0 = acc[mt][nt][half*2 + 0];
                float v1 = acc[mt][nt][half*2 + 1];
                if (mode == 1) {
                    float2 bi = *(const float2*)&bias[n];
                    *(float2*)&Cout[(size_t)m * DIMM + n] =
                        make_float2(v0 + bi.x, v1 + bi.y);
                } else {
                    int part = n >> 10, h = (n >> 6) & 15, d = n & 63;
                    int b = m >> 11, s = m & 2047;
                    int bh = b * NH + h;
                    if (part == 0) { v0 *= 0.125f; v1 *= 0.125f; }
                    uint32_t h2 = pack2(v0, v1);
                    uint32_t l2 = pack2(v0 - lo_f(h2), v1 - hi_f(h2));
                    if (part == 0) {          // Q: [hi | lo | hi], pre-scaled
                        size_t base = ((size_t)bh * SEQ + s) * 192 + d;
                        *(uint32_t*)&g_q[base]       = h2;
                        *(uint32_t*)&g_q[base + 64]  = l2;
                        *(uint32_t*)&g_q[base + 128] = h2;
                    } else if (part == 1) {   // K: [hi | hi | lo]
                        size_t base = ((size_t)bh * SEQ + s) * 192 + d;
                        *(uint32_t*)&g_k[base]       = h2;
                        *(uint32_t*)&g_k[base + 64]  = h2;
                        *(uint32_t*)&g_k[base + 128] = l2;
                    } else {                  // V: planes hi / lo
                        size_t base = (((size_t)bh * 2) * SEQ + s) * 64 + d;
                        *(uint32_t*)&g_v[base]                 = h2;
                        *(uint32_t*)&g_v[base + (size_t)SEQ*64] = l2;
                    }
                }
            }
        }
    }
}

// ---------------- flash attention with mma.sync (static smem only) ----------
// Block: 256 thr (8 warps), BR=128 q-rows (16/warp), BC=64 keys/iter.
// Q held in registers; static shared = 44032 B < 48 KB.
__global__ __launch_bounds__(256) void attn_mma_kernel()
{
    __shared__ __align__(16) bf16 Ks[64][200];
    __shared__ __align__(16) bf16 Vh[64][72];
    __shared__ __align__(16) bf16 Vl[64][72];

    const int t    = threadIdx.x;
    const int wid  = t >> 5;
    const int lane = t & 31;
    const int bh   = blockIdx.y;
    const int q0   = blockIdx.x * 128;

    const bf16* Qg = g_q + (size_t)bh * SEQ * 192;
    const bf16* Kg = g_k + (size_t)bh * SEQ * 192;
    const bf16* Vg = g_v + (size_t)bh * 2 * SEQ * 64;

    const uint32_t ksBase = smem_u32(&Ks[0][0]);
    const uint32_t vhBase = smem_u32(&Vh[0][0]);
    const uint32_t vlBase = smem_u32(&Vl[0][0]);

    // ---- Q A-fragments directly from gmem (one-time) ----
    uint32_t qfr[12][4];
    {
        const bf16* Qr = Qg + (size_t)(q0 + 16*wid + (lane >> 2)) * 192 + (lane & 3) * 2;
#pragma unroll
        for (int ks = 0; ks < 12; ks++) {
            qfr[ks][0] = *(const uint32_t*)(Qr + ks*16);
            qfr[ks][1] = *(const uint32_t*)(Qr + 8*192 + ks*16);
            qfr[ks][2] = *(const uint32_t*)(Qr + ks*16 + 8);
            qfr[ks][3] = *(const uint32_t*)(Qr + 8*192 + ks*16 + 8);
        }
    }

    float acc_o[8][4];
#pragma unroll
    for (int i = 0; i < 8; i++)
#pragma unroll
        for (int j = 0; j < 4; j++) acc_o[i][j] = 0.0f;
    float m_lo = -1e30f, m_hi = -1e30f, l_lo = 0.0f, l_hi = 0.0f;

    for (int j0 = 0; j0 < SEQ; j0 += 64) {
        __syncthreads();                  // previous tile fully consumed
#pragma unroll
        for (int i = 0; i < 6; i++) {
            int idx = t + i * 256;        // 1536 8-elem chunks
            int r = idx / 24, c = idx % 24;
            *(uint4*)&Ks[r][c*8] =
                *(const uint4*)(Kg + (size_t)(j0 + r) * 192 + c*8);
        }
#pragma unroll
        for (int i = 0; i < 2; i++) {
            int idx = t + i * 256;        // 512
            int r = idx / 8, c = idx % 8;
            *(uint4*)&Vh[r][c*8] =
                *(const uint4*)(Vg + (size_t)(j0 + r) * 64 + c*8);
            *(uint4*)&Vl[r][c*8] =
                *(const uint4*)(Vg + (size_t)SEQ*64 + (size_t)(j0 + r) * 64 + c*8);
        }
        __syncthreads();

        // ---- S = Q' @ K'^T  (d'=192 contraction) ----
        float sc[8][4];
#pragma unroll
        for (int i = 0; i < 8; i++)
#pragma unroll
            for (int j = 0; j < 4; j++) sc[i][j] = 0.0f;

#pragma unroll
        for (int ks = 0; ks < 12; ks++) {
            const int k0 = ks * 16;
#pragma unroll
            for (int ntp = 0; ntp < 8; ntp += 2) {
                uint32_t tmp[4];
                ldsm_x4(tmp, ksBase +
                    (((ntp*8 + (lane >> 4)*8 + (lane & 7)) * 200)
                     + k0 + ((lane >> 3) & 1) * 8) * 2);
                mma_bf16(sc[ntp],   qfr[ks], tmp);
                mma_bf16(sc[ntp+1], qfr[ks], tmp + 2);
            }
        }

        // ---- online softmax (rows: lane>>2 and +8) ----
        float mx0 = -1e30f, mx1 = -1e30f;
#pragma unroll
        for (int nt = 0; nt < 8; nt++) {
            mx0 = fmaxf(mx0, fmaxf(sc[nt][0], sc[nt][1]));
            mx1 = fmaxf(mx1, fmaxf(sc[nt][2], sc[nt][3]));
        }
        mx0 = fmaxf(mx0, __shfl_xor_sync(0xffffffffu, mx0, 1));
        mx0 = fmaxf(mx0, __shfl_xor_sync(0xffffffffu, mx0, 2));
        mx1 = fmaxf(mx1, __shfl_xor_sync(0xffffffffu, mx1, 1));
        mx1 = fmaxf(mx1, __shfl_xor_sync(0xffffffffu, mx1, 2));
        float mn0 = fmaxf(m_lo, mx0), mn1 = fmaxf(m_hi, mx1);
        float f0 = __expf(m_lo - mn0), f1 = __expf(m_hi - mn1);
        m_lo = mn0; m_hi = mn1;

        float s0 = 0.0f, s1 = 0.0f;
#pragma unroll
        for (int nt = 0; nt < 8; nt++) {
            sc[nt][0] = __expf(sc[nt][0] - mn0); s0 += sc[nt][0];
            sc[nt][1] = __expf(sc[nt][1] - mn0); s0 += sc[nt][1];
            sc[nt][2] = __expf(sc[nt][2] - mn1); s1 += sc[nt][2];
            sc[nt][3] = __expf(sc[nt][3] - mn1); s1 += sc[nt][3];
        }
        s0 += __shfl_xor_sync(0xffffffffu, s0, 1);
        s0 += __shfl_xor_sync(0xffffffffu, s0, 2);
        s1 += __shfl_xor_sync(0xffffffffu, s1, 1);
        s1 += __shfl_xor_sync(0xffffffffu, s1, 2);
        l_lo = l_lo * f0 + s0;
        l_hi = l_hi * f1 + s1;
#pragma unroll
        for (int nt = 0; nt < 8; nt++) {
            acc_o[nt][0] *= f0; acc_o[nt][1] *= f0;
            acc_o[nt][2] *= f1; acc_o[nt][3] *= f1;
        }

        // ---- P fragments (C-layout == A-frag layout) ----
        uint32_t aph[4][4], apl[4][4];
#pragma unroll
        for (int kt = 0; kt < 4; kt++) {
            aph[kt][0] = pack2(sc[2*kt][0],   sc[2*kt][1]);
            aph[kt][1] = pack2(sc[2*kt][2],   sc[2*kt][3]);
            aph[kt][2] = pack2(sc[2*kt+1][0], sc[2*kt+1][1]);
            aph[kt][3] = pack2(sc[2*kt+1][2], sc[2*kt+1][3]);
            apl[kt][0] = pack2(sc[2*kt][0]   - lo_f(aph[kt][0]), sc[2*kt][1]   - hi_f(aph[kt][0]));
            apl[kt][1] = pack2(sc[2*kt][2]   - lo_f(aph[kt][1]), sc[2*kt][3]   - hi_f(aph[kt][1]));
            apl[kt][2] = pack2(sc[2*kt+1][0] - lo_f(aph[kt][2]), sc[2*kt+1][1] - hi_f(aph[kt][2]));
            apl[kt][3] = pack2(sc[2*kt+1][2] - lo_f(aph[kt][3]), sc[2*kt+1][3] - hi_f(aph[kt][3]));
        }

        // ---- O += P @ V  (ph*vh + pl*vh + ph*vl) ----
#pragma unroll
        for (int kt = 0; kt < 4; kt++) {
#pragma unroll
            for (int ntp = 0; ntp < 8; ntp += 2) {
                uint32_t bh4[4], bl4[4];
                uint32_t voff = (((kt*16 + (lane & 15)) * 72)
                                 + ntp*8 + (lane >> 4) * 8) * 2;
                ldsm_x4_t(bh4, vhBase + voff);
                ldsm_x4_t(bl4, vlBase + voff);
                mma_bf16(acc_o[ntp],   aph[kt], bh4);
                mma_bf16(acc_o[ntp],   apl[kt], bh4);
                mma_bf16(acc_o[ntp],   aph[kt], bl4);
                mma_bf16(acc_o[ntp+1], aph[kt], bh4 + 2);
                mma_bf16(acc_o[ntp+1], apl[kt], bh4 + 2);
                mma_bf16(acc_o[ntp+1], aph[kt], bl4 + 2);
            }
        }
    }

    // ---- finalize: reference reshape semantics (flat view of [B,H,S,D]):
    //   (b,h,s,d) -> row b*2048 + h*128 + (s>>4), col (s&15)*64 + d
    float inv0 = 1.0f / l_lo, inv1 = 1.0f / l_hi;
    const int b = bh >> 4, h = bh & 15;
    const int s_base = q0 + 16*wid + (lane >> 2);
#pragma unroll
    for (int nt = 0; nt < 8; nt++) {
        int d = nt*8 + 2*(lane & 3);
#pragma unroll
        for (int half = 0; half < 2; half++) {
            int s = s_base + half * 8;
            int m   = b * 2048 + h * 128 + (s >> 4);
            int col = (s & 15) * 64 + d;
            float v0 = acc_o[nt][half*2 + 0] * (half ? inv1 : inv0);
            float v1 = acc_o[nt][half*2 + 1] * (half ? inv1 : inv0);
            uint32_t h2 = pack2(v0, v1);
            uint32_t l2 = pack2(v0 - lo_f(h2), v1 - hi_f(h2));
            size_t base = (size_t)m * GK + col;
            *(uint32_t*)&g_Ax[base]        = h2;
            *(uint32_t*)&g_Ax[base + 1024] = l2;
            *(uint32_t*)&g_Ax[base + 2048] = h2;
        }
    }
}

// ---------------------------------------------------------------------------
extern "C" void kernel_launch(void* const* d_in, const int* in_sizes, int n_in,
                              void* d_out, int out_size)
{
    const float* x     = (const float*)d_in[0];
    const float* w_qkv = (const float*)d_in[1];
    const float* w_out = (const float*)d_in[2];
    const float* b_out = (const float*)d_in[3];
    float* out = (float*)d_out;

    conv_split_kernel<<<MTOT, 256>>>(x);
    conv_w_kernel<<<dim3(32, 96), dim3(32, 32)>>>(w_qkv, 3072, 0);
    conv_w_kernel<<<dim3(32, 32), dim3(32, 32)>>>(w_out, 1024, 1);

    // GEMM1: qkv -> split q/k/v layouts
    mma_gemm_kernel<<<dim3(3072/128, MTOT/128), 256>>>(nullptr, nullptr, 0);

    // attention (writes split GEMM2 input into g_Ax)
    attn_mma_kernel<<<dim3(SEQ/128, 64), 256>>>();

    // GEMM2: + bias -> out
    mma_gemm_kernel<<<dim3(DIMM/128, MTOT/128), 256>>>(b_out, out, 1);
}